// round 1
// baseline (speedup 1.0000x reference)
#include <cuda_runtime.h>
#include <cfloat>
#include <math.h>

#define Cdim 256
#define Hdim 128
#define Wdim 128
#define HW   16384
#define Bdim 8
#define ROWS 8
#define TILE 1024          // ROWS * Wdim
#define BPB  16            // blocks per batch = HW / TILE

// ---------------- scratch (device globals; no allocation allowed) ----------
__device__ float g_u[Cdim];           // v_w^T w3
__device__ float g_t3bias;            // w3 . v_b
__device__ float g_t3s[Bdim*HW];      // t3 per pixel
__device__ float g_s[Bdim*HW];        // final spatial sigmoid map
__device__ float g_xkp[Bdim*BPB*Cdim];// per-block partial xk (unnormalized, local max)
__device__ float g_Mblk[Bdim*BPB];
__device__ float g_Zblk[Bdim*BPB];
__device__ float g_hmax[Bdim*Hdim];
__device__ float g_havg[Bdim*Hdim];
__device__ float g_wmax[Bdim*Wdim];
__device__ float g_wsum[Bdim*Wdim];
__device__ float g_cf[Bdim*Cdim];     // channel_fea

// ---------------- helpers ----------------
__device__ __forceinline__ float warpMax(float v){
  #pragma unroll
  for (int o=16;o;o>>=1) v = fmaxf(v, __shfl_xor_sync(0xffffffffu, v, o));
  return v;
}
__device__ __forceinline__ float warpSum(float v){
  #pragma unroll
  for (int o=16;o;o>>=1) v += __shfl_xor_sync(0xffffffffu, v, o);
  return v;
}
__device__ __forceinline__ void atomicMaxF(float* addr, float val){
  int* ia = (int*)addr;
  int old = *ia;
  while (__int_as_float(old) < val){
    int assumed = old;
    old = atomicCAS(ia, assumed, __float_as_int(val));
    if (old == assumed) break;
  }
}
__device__ __forceinline__ float sigmoidf(float x){ return 1.f/(1.f+expf(-x)); }

// ---------------- K0: precompute u, t3bias; init w-pools ----------------
__global__ __launch_bounds__(256)
void k0_init(const float* __restrict__ vw, const float* __restrict__ vb,
             const float* __restrict__ w3){
  int t = threadIdx.x;
  float u = 0.f;
  #pragma unroll 8
  for (int o=0;o<Cdim;o++) u = fmaf(w3[o], vw[o*Cdim + t], u);
  g_u[t] = u;
  if (t==0){
    float tb = 0.f;
    for (int o=0;o<Cdim;o++) tb = fmaf(w3[o], vb[o], tb);
    g_t3bias = tb;
  }
  for (int i=t;i<Bdim*Wdim;i+=256){ g_wmax[i] = -FLT_MAX; g_wsum[i] = 0.f; }
}

// ---------------- K1: fused main pass over x ----------------
// Block = 8 full rows (1024 pixels) of one batch, all 256 channels.
// Pass A (c-loop, coalesced float4): logits, t3, per-position max/sum over c.
// Then: exact h pools (block owns full rows), partial w pools (atomic),
// local softmax (M_blk, Z_blk, e[] in smem), then pass B re-reads the tile
// (mostly L2 hits) accumulating per-block partial xk per channel.
__global__ __launch_bounds__(256)
void k1_main(const float* __restrict__ x, const float* __restrict__ kwp,
             const float* __restrict__ kbp){
  const int j = blockIdx.x, b = blockIdx.y;
  const int t = threadIdx.x, warp = t>>5, lane = t&31;

  __shared__ float s_kw[Cdim], s_u[Cdim];
  __shared__ float s_le[TILE];                 // exp(l - M_blk)
  __shared__ float s_cm[ROWS][Wdim], s_cs[ROWS][Wdim];
  __shared__ float s_redA[8], s_redB[8];

  s_kw[t] = kwp[t];
  s_u[t]  = g_u[t];
  __syncthreads();

  const float* xb = x + (size_t)b*Cdim*HW + j*TILE;

  float4 aL = make_float4(0,0,0,0), aT = make_float4(0,0,0,0);
  float4 pm = make_float4(-FLT_MAX,-FLT_MAX,-FLT_MAX,-FLT_MAX);
  float4 ps = make_float4(0,0,0,0);

  #pragma unroll 4
  for (int c=0;c<Cdim;c++){
    float4 xv = *(const float4*)(xb + (size_t)c*HW + 4*t);
    float kw = s_kw[c], uc = s_u[c];
    aL.x = fmaf(kw, xv.x, aL.x); aL.y = fmaf(kw, xv.y, aL.y);
    aL.z = fmaf(kw, xv.z, aL.z); aL.w = fmaf(kw, xv.w, aL.w);
    aT.x = fmaf(uc, xv.x, aT.x); aT.y = fmaf(uc, xv.y, aT.y);
    aT.z = fmaf(uc, xv.z, aT.z); aT.w = fmaf(uc, xv.w, aT.w);
    pm.x = fmaxf(pm.x, xv.x); pm.y = fmaxf(pm.y, xv.y);
    pm.z = fmaxf(pm.z, xv.z); pm.w = fmaxf(pm.w, xv.w);
    ps.x += xv.x; ps.y += xv.y; ps.z += xv.z; ps.w += xv.w;
  }

  const float kb = kbp[0];
  const float l0 = aL.x+kb, l1 = aL.y+kb, l2 = aL.z+kb, l3 = aL.w+kb;

  // t3 out
  {
    float t3b = g_t3bias;
    float4 tv = make_float4(aT.x+t3b, aT.y+t3b, aT.z+t3b, aT.w+t3b);
    *(float4*)(g_t3s + (size_t)b*HW + j*TILE + 4*t) = tv;
  }

  // h pools: warp == row, block owns full (c, w) extent -> exact
  {
    float rm = fmaxf(fmaxf(pm.x,pm.y), fmaxf(pm.z,pm.w));
    float rs = ps.x+ps.y+ps.z+ps.w;
    rm = warpMax(rm); rs = warpSum(rs);
    if (lane==0){
      int h = j*ROWS + warp;
      g_hmax[b*Hdim + h] = rm;
      g_havg[b*Hdim + h] = rs * (1.f/(Cdim*Wdim));
    }
  }

  // w pools: per-column partial over (c, 8 rows), atomic combine across blocks
  s_cm[warp][4*lane+0] = pm.x; s_cm[warp][4*lane+1] = pm.y;
  s_cm[warp][4*lane+2] = pm.z; s_cm[warp][4*lane+3] = pm.w;
  s_cs[warp][4*lane+0] = ps.x; s_cs[warp][4*lane+1] = ps.y;
  s_cs[warp][4*lane+2] = ps.z; s_cs[warp][4*lane+3] = ps.w;
  __syncthreads();
  if (t < Wdim){
    float cm = s_cm[0][t], cs = s_cs[0][t];
    #pragma unroll
    for (int r=1;r<ROWS;r++){ cm = fmaxf(cm, s_cm[r][t]); cs += s_cs[r][t]; }
    atomicMaxF(&g_wmax[b*Wdim+t], cm);
    atomicAdd(&g_wsum[b*Wdim+t], cs);
  }

  // local softmax over the 1024 logits
  float lm = fmaxf(fmaxf(l0,l1), fmaxf(l2,l3));
  lm = warpMax(lm);
  if (lane==0) s_redA[warp] = lm;
  __syncthreads();
  float M = -FLT_MAX;
  #pragma unroll
  for (int r=0;r<8;r++) M = fmaxf(M, s_redA[r]);

  float e0 = expf(l0-M), e1 = expf(l1-M), e2 = expf(l2-M), e3 = expf(l3-M);
  s_le[4*t+0]=e0; s_le[4*t+1]=e1; s_le[4*t+2]=e2; s_le[4*t+3]=e3;
  float z = warpSum(e0+e1+e2+e3);
  if (lane==0) s_redB[warp] = z;
  __syncthreads();
  if (t==0){
    float Z = 0.f;
    #pragma unroll
    for (int r=0;r<8;r++) Z += s_redB[r];
    g_Mblk[b*BPB+j] = M;
    g_Zblk[b*BPB+j] = Z;
  }
  // s_le writes are ordered before xk pass by the sync above

  // xk pass: warp w handles 32 channels, coalesced float4 re-read (L2 hot)
  const float4* e4 = (const float4*)s_le;
  #pragma unroll 1
  for (int k=0;k<32;k++){
    int c = warp*32 + k;
    const float4* xc = (const float4*)(x + (size_t)(b*Cdim + c)*HW + j*TILE);
    float acc = 0.f;
    #pragma unroll
    for (int q=0;q<8;q++){
      float4 xv = xc[q*32 + lane];
      float4 ev = e4[q*32 + lane];
      acc = fmaf(xv.x, ev.x, acc); acc = fmaf(xv.y, ev.y, acc);
      acc = fmaf(xv.z, ev.z, acc); acc = fmaf(xv.w, ev.w, acc);
    }
    acc = warpSum(acc);
    if (lane==0) g_xkp[(size_t)(b*BPB+j)*Cdim + c] = acc;
  }
}

// ---------------- K2: per-batch combine (tiny) ----------------
__global__ __launch_bounds__(256)
void k2_combine(const float* __restrict__ vw, const float* __restrict__ vb,
                const float* __restrict__ w1, const float* __restrict__ b1,
                const float* __restrict__ w2, const float* __restrict__ b2,
                const float* __restrict__ b3p){
  const int b = blockIdx.x, t = threadIdx.x;
  __shared__ float s_alpha[BPB], s_xk[Cdim], s_ah[Hdim], s_aw[Wdim];

  if (t==0){
    float M = -FLT_MAX;
    for (int jj=0;jj<BPB;jj++) M = fmaxf(M, g_Mblk[b*BPB+jj]);
    float Z = 0.f;
    for (int jj=0;jj<BPB;jj++) Z += g_Zblk[b*BPB+jj]*expf(g_Mblk[b*BPB+jj]-M);
    float invZ = 1.f/Z;
    for (int jj=0;jj<BPB;jj++) s_alpha[jj] = expf(g_Mblk[b*BPB+jj]-M)*invZ;
  }
  if (t < Hdim){
    s_ah[t] = sigmoidf(w1[0]*g_hmax[b*Hdim+t] + w1[1]*g_havg[b*Hdim+t] + b1[0]);
    s_aw[t] = sigmoidf(w2[0]*g_wmax[b*Wdim+t] + w2[1]*(g_wsum[b*Wdim+t]*(1.f/32768.f)) + b2[0]);
  }
  __syncthreads();

  float xk = 0.f;
  #pragma unroll
  for (int jj=0;jj<BPB;jj++)
    xk = fmaf(g_xkp[(size_t)(b*BPB+jj)*Cdim + t], s_alpha[jj], xk);
  s_xk[t] = xk;
  __syncthreads();

  float cf = vb[t];
  #pragma unroll 8
  for (int c2=0;c2<Cdim;c2++) cf = fmaf(vw[t*Cdim + c2], s_xk[c2], cf);
  g_cf[b*Cdim + t] = cf;

  const float b3 = b3p[0];
  for (int n=t; n<HW; n+=256){
    float arg = (s_ah[n>>7] + s_aw[n&127]) * g_t3s[(size_t)b*HW + n] + b3;
    g_s[(size_t)b*HW + n] = sigmoidf(arg);
  }
}

// ---------------- K3: streaming epilogue ----------------
__global__ __launch_bounds__(256)
void k3_final(const float* __restrict__ x, float* __restrict__ out){
  size_t v = (size_t)blockIdx.x*256 + threadIdx.x;   // float4 index
  float4 xv = ((const float4*)x)[v];
  int n4 = (int)(v & 4095);
  int c  = (int)((v>>12) & 255);
  int b  = (int)(v>>20);
  float4 s4 = ((const float4*)g_s)[(size_t)b*4096 + n4];
  float cf = __ldg(&g_cf[b*Cdim + c]);
  float4 o;
  o.x = fmaf(s4.x, cf, xv.x);
  o.y = fmaf(s4.y, cf, xv.y);
  o.z = fmaf(s4.z, cf, xv.z);
  o.w = fmaf(s4.w, cf, xv.w);
  ((float4*)out)[v] = o;
}

// ---------------- launch ----------------
extern "C" void kernel_launch(void* const* d_in, const int* in_sizes, int n_in,
                              void* d_out, int out_size){
  const float* x  = (const float*)d_in[0];
  const float* vw = (const float*)d_in[1];
  const float* vb = (const float*)d_in[2];
  const float* kw = (const float*)d_in[3];
  const float* kb = (const float*)d_in[4];
  const float* w1 = (const float*)d_in[5];
  const float* b1 = (const float*)d_in[6];
  const float* w2 = (const float*)d_in[7];
  const float* b2 = (const float*)d_in[8];
  const float* w3 = (const float*)d_in[9];
  const float* b3 = (const float*)d_in[10];
  float* out = (float*)d_out;

  k0_init<<<1,256>>>(vw, vb, w3);
  dim3 g1(BPB, Bdim);
  k1_main<<<g1,256>>>(x, kw, kb);
  k2_combine<<<Bdim,256>>>(vw, vb, w1, b1, w2, b2, b3);
  int nvec4 = Bdim*Cdim*HW/4;           // 8388608
  k3_final<<<nvec4/256,256>>>(x, out);
}

// round 2
// speedup vs baseline: 1.4196x; 1.4196x over previous
#include <cuda_runtime.h>
#include <cfloat>
#include <math.h>

#define Cdim 256
#define Hdim 128
#define Wdim 128
#define HW   16384
#define Bdim 8
#define NCG  4          // channel groups
#define CPG  64         // channels per group
#define NT   16         // pixel tiles per batch (1024 px each)
#define TPX  1024       // pixels per tile

// ---------------- scratch (device globals) ----------------
__device__ float g_u[Cdim];             // v_w^T w3
__device__ float g_t3bias;              // w3 . v_b
__device__ float g_lp[NCG*Bdim*HW];     // logit partials per cgroup
__device__ float g_tp[NCG*Bdim*HW];     // t3 partials per cgroup
__device__ float g_e[Bdim*HW];          // exp(l - M_tile)
__device__ float g_t3s[Bdim*HW];        // t3
__device__ float g_s[Bdim*HW];          // final spatial sigmoid map
__device__ float g_hp_max[NCG*Bdim*Hdim];
__device__ float g_hp_sum[NCG*Bdim*Hdim];
__device__ float g_wp_max[NT*NCG*Bdim*Wdim];
__device__ float g_wp_sum[NT*NCG*Bdim*Wdim];
__device__ float g_Mt[Bdim*NT];
__device__ float g_Zt[Bdim*NT];
__device__ float g_alpha[Bdim*NT];      // exp(Mt - M)/Z
__device__ float g_ah[Bdim*Hdim];
__device__ float g_aw[Bdim*Wdim];
__device__ float g_xkp[Bdim*Cdim*NT];   // xk partial per tile
__device__ float g_cf[Bdim*Cdim];       // channel_fea

// ---------------- helpers ----------------
__device__ __forceinline__ float warpMax(float v){
  #pragma unroll
  for (int o=16;o;o>>=1) v = fmaxf(v, __shfl_xor_sync(0xffffffffu, v, o));
  return v;
}
__device__ __forceinline__ float warpSum(float v){
  #pragma unroll
  for (int o=16;o;o>>=1) v += __shfl_xor_sync(0xffffffffu, v, o);
  return v;
}
__device__ __forceinline__ float sigmoidf_(float x){ return 1.f/(1.f+expf(-x)); }

// ---------------- K0: precompute u, t3bias ----------------
__global__ __launch_bounds__(256)
void k0_init(const float* __restrict__ vw, const float* __restrict__ vb,
             const float* __restrict__ w3){
  int t = threadIdx.x;
  float u = 0.f;
  #pragma unroll 8
  for (int o=0;o<Cdim;o++) u = fmaf(w3[o], vw[o*Cdim + t], u);
  g_u[t] = u;
  if (t==0){
    float tb = 0.f;
    for (int o=0;o<Cdim;o++) tb = fmaf(w3[o], vb[o], tb);
    g_t3bias = tb;
  }
}

// ---------------- K1: partial pass over x ----------------
// grid (NT, NCG, Bdim), 256 thr. Block: 64 channels x 1024 px (8 rows).
__global__ __launch_bounds__(256)
void k1_partial(const float* __restrict__ x, const float* __restrict__ kwp){
  const int jt = blockIdx.x, cg = blockIdx.y, b = blockIdx.z;
  const int t = threadIdx.x, warp = t>>5, lane = t&31;

  __shared__ float s_kw[CPG], s_u[CPG];
  __shared__ float s_cm[8][Wdim], s_cs[8][Wdim];

  if (t < CPG){ s_kw[t] = kwp[cg*CPG + t]; s_u[t] = g_u[cg*CPG + t]; }
  __syncthreads();

  const float* xb = x + ((size_t)(b*Cdim + cg*CPG))*HW + jt*TPX + 4*t;

  float4 aL = make_float4(0,0,0,0), aT = make_float4(0,0,0,0);
  float4 pm = make_float4(-FLT_MAX,-FLT_MAX,-FLT_MAX,-FLT_MAX);
  float4 ps = make_float4(0,0,0,0);

  #pragma unroll 8
  for (int c=0;c<CPG;c++){
    float4 xv = *(const float4*)(xb + (size_t)c*HW);
    float kw = s_kw[c], uc = s_u[c];
    aL.x = fmaf(kw, xv.x, aL.x); aL.y = fmaf(kw, xv.y, aL.y);
    aL.z = fmaf(kw, xv.z, aL.z); aL.w = fmaf(kw, xv.w, aL.w);
    aT.x = fmaf(uc, xv.x, aT.x); aT.y = fmaf(uc, xv.y, aT.y);
    aT.z = fmaf(uc, xv.z, aT.z); aT.w = fmaf(uc, xv.w, aT.w);
    pm.x = fmaxf(pm.x, xv.x); pm.y = fmaxf(pm.y, xv.y);
    pm.z = fmaxf(pm.z, xv.z); pm.w = fmaxf(pm.w, xv.w);
    ps.x += xv.x; ps.y += xv.y; ps.z += xv.z; ps.w += xv.w;
  }

  size_t pbase = ((size_t)(cg*Bdim + b))*HW + jt*TPX + 4*t;
  *(float4*)(g_lp + pbase) = aL;
  *(float4*)(g_tp + pbase) = aT;

  // h partial: warp == row within tile
  {
    float rm = fmaxf(fmaxf(pm.x,pm.y), fmaxf(pm.z,pm.w));
    float rs = ps.x+ps.y+ps.z+ps.w;
    rm = warpMax(rm); rs = warpSum(rs);
    if (lane==0){
      int h = jt*8 + warp;
      g_hp_max[(cg*Bdim + b)*Hdim + h] = rm;
      g_hp_sum[(cg*Bdim + b)*Hdim + h] = rs;
    }
  }

  // w partial: reduce 8 rows per column
  s_cm[warp][4*lane+0] = pm.x; s_cm[warp][4*lane+1] = pm.y;
  s_cm[warp][4*lane+2] = pm.z; s_cm[warp][4*lane+3] = pm.w;
  s_cs[warp][4*lane+0] = ps.x; s_cs[warp][4*lane+1] = ps.y;
  s_cs[warp][4*lane+2] = ps.z; s_cs[warp][4*lane+3] = ps.w;
  __syncthreads();
  if (t < Wdim){
    float cm = s_cm[0][t], cs = s_cs[0][t];
    #pragma unroll
    for (int r=1;r<8;r++){ cm = fmaxf(cm, s_cm[r][t]); cs += s_cs[r][t]; }
    int pi = ((jt*NCG + cg)*Bdim + b)*Wdim + t;
    g_wp_max[pi] = cm; g_wp_sum[pi] = cs;
  }
}

// ---------------- K2a: combine partials, tile softmax stats ----------------
// grid (NT, Bdim), 256 thr
__global__ __launch_bounds__(256)
void k2a_logits(const float* __restrict__ kbp){
  const int jt = blockIdx.x, b = blockIdx.y;
  const int t = threadIdx.x, warp = t>>5, lane = t&31;
  __shared__ float s_redA[8], s_redB[8];

  size_t off = (size_t)jt*TPX + 4*t;
  float4 l = make_float4(0,0,0,0), t3 = make_float4(0,0,0,0);
  #pragma unroll
  for (int cg=0; cg<NCG; cg++){
    size_t pbase = ((size_t)(cg*Bdim + b))*HW + off;
    float4 lp = *(const float4*)(g_lp + pbase);
    float4 tp = *(const float4*)(g_tp + pbase);
    l.x += lp.x; l.y += lp.y; l.z += lp.z; l.w += lp.w;
    t3.x += tp.x; t3.y += tp.y; t3.z += tp.z; t3.w += tp.w;
  }
  const float kb = kbp[0], tb = g_t3bias;
  l.x += kb; l.y += kb; l.z += kb; l.w += kb;
  t3.x += tb; t3.y += tb; t3.z += tb; t3.w += tb;
  *(float4*)(g_t3s + (size_t)b*HW + off) = t3;

  // tile max
  float lm = fmaxf(fmaxf(l.x,l.y), fmaxf(l.z,l.w));
  lm = warpMax(lm);
  if (lane==0) s_redA[warp] = lm;
  __syncthreads();
  float M = s_redA[0];
  #pragma unroll
  for (int r=1;r<8;r++) M = fmaxf(M, s_redA[r]);

  float4 e;
  e.x = expf(l.x-M); e.y = expf(l.y-M); e.z = expf(l.z-M); e.w = expf(l.w-M);
  *(float4*)(g_e + (size_t)b*HW + off) = e;
  float z = warpSum(e.x+e.y+e.z+e.w);
  if (lane==0) s_redB[warp] = z;
  __syncthreads();
  if (t==0){
    float Z = 0.f;
    #pragma unroll
    for (int r=0;r<8;r++) Z += s_redB[r];
    g_Mt[b*NT + jt] = M;
    g_Zt[b*NT + jt] = Z;
  }
}

// ---------------- K2b: per-batch combine: alphas + attentions ----------------
// grid (Bdim), 256 thr
__global__ __launch_bounds__(256)
void k2b_combine(const float* __restrict__ w1, const float* __restrict__ b1,
                 const float* __restrict__ w2, const float* __restrict__ b2){
  const int b = blockIdx.x, t = threadIdx.x;
  __shared__ float sM, sZ;
  if (t==0){
    float M = -FLT_MAX;
    for (int j=0;j<NT;j++) M = fmaxf(M, g_Mt[b*NT+j]);
    float Z = 0.f;
    for (int j=0;j<NT;j++) Z += g_Zt[b*NT+j]*expf(g_Mt[b*NT+j]-M);
    sM = M; sZ = Z;
  }
  __syncthreads();
  if (t < NT) g_alpha[b*NT + t] = expf(g_Mt[b*NT+t]-sM)/sZ;
  if (t < Hdim){
    float hm = -FLT_MAX, hs = 0.f;
    #pragma unroll
    for (int cg=0; cg<NCG; cg++){
      hm = fmaxf(hm, g_hp_max[(cg*Bdim+b)*Hdim + t]);
      hs += g_hp_sum[(cg*Bdim+b)*Hdim + t];
    }
    g_ah[b*Hdim+t] = sigmoidf_(w1[0]*hm + w1[1]*(hs*(1.f/32768.f)) + b1[0]);
  } else {
    int w = t - 128;
    float wm = -FLT_MAX, ws = 0.f;
    for (int p=0; p<NT*NCG; p++){
      wm = fmaxf(wm, g_wp_max[(p*Bdim+b)*Wdim + w]);
      ws += g_wp_sum[(p*Bdim+b)*Wdim + w];
    }
    g_aw[b*Wdim+w] = sigmoidf_(w2[0]*wm + w2[1]*(ws*(1.f/32768.f)) + b2[0]);
  }
}

// ---------------- K2c: s map ----------------
// grid (NT, Bdim), 256 thr
__global__ __launch_bounds__(256)
void k2c_smap(const float* __restrict__ b3p){
  const int jt = blockIdx.x, b = blockIdx.y;
  const int t = threadIdx.x;
  const float b3 = b3p[0];
  int n = jt*TPX + 4*t;
  int h = n >> 7, w0 = n & 127;
  float ah = g_ah[b*Hdim + h];
  float4 t3 = *(const float4*)(g_t3s + (size_t)b*HW + n);
  float4 s;
  s.x = sigmoidf_((ah + g_aw[b*Wdim + w0+0])*t3.x + b3);
  s.y = sigmoidf_((ah + g_aw[b*Wdim + w0+1])*t3.y + b3);
  s.z = sigmoidf_((ah + g_aw[b*Wdim + w0+2])*t3.z + b3);
  s.w = sigmoidf_((ah + g_aw[b*Wdim + w0+3])*t3.w + b3);
  *(float4*)(g_s + (size_t)b*HW + n) = s;
}

// ---------------- K3: xk = softmax-weighted spatial sum of x ----------------
// grid (NT, NCG, Bdim), 256 thr. Block: 64 channels x 1024 px.
__global__ __launch_bounds__(256)
void k3_xk(const float* __restrict__ x){
  const int jt = blockIdx.x, cg = blockIdx.y, b = blockIdx.z;
  const int t = threadIdx.x, warp = t>>5, lane = t&31;
  __shared__ float s_k[TPX];

  float alpha = g_alpha[b*NT + jt];
  {
    float4 e = *(const float4*)(g_e + (size_t)b*HW + jt*TPX + 4*t);
    float4 kk = make_float4(e.x*alpha, e.y*alpha, e.z*alpha, e.w*alpha);
    *(float4*)(s_k + 4*t) = kk;
  }
  __syncthreads();

  const float4* k4 = (const float4*)s_k;
  #pragma unroll 1
  for (int kk=0; kk<8; kk++){
    int c = cg*CPG + warp*8 + kk;
    const float4* xc = (const float4*)(x + ((size_t)(b*Cdim + c))*HW + jt*TPX);
    float acc = 0.f;
    #pragma unroll
    for (int i=0;i<8;i++){
      float4 xv = xc[i*32 + lane];
      float4 ev = k4[i*32 + lane];
      acc = fmaf(xv.x, ev.x, acc); acc = fmaf(xv.y, ev.y, acc);
      acc = fmaf(xv.z, ev.z, acc); acc = fmaf(xv.w, ev.w, acc);
    }
    acc = warpSum(acc);
    if (lane==0) g_xkp[((size_t)(b*Cdim + c))*NT + jt] = acc;
  }
}

// ---------------- K4: channel_fea = vw @ xk + vb ----------------
// grid (Bdim), 256 thr
__global__ __launch_bounds__(256)
void k4_cf(const float* __restrict__ vw, const float* __restrict__ vb){
  const int b = blockIdx.x, t = threadIdx.x;
  __shared__ float s_xk[Cdim];
  float xk = 0.f;
  #pragma unroll
  for (int j=0;j<NT;j++) xk += g_xkp[((size_t)(b*Cdim + t))*NT + j];
  s_xk[t] = xk;
  __syncthreads();
  float cf = vb[t];
  #pragma unroll 8
  for (int c=0;c<Cdim;c++) cf = fmaf(vw[t*Cdim + c], s_xk[c], cf);
  g_cf[b*Cdim + t] = cf;
}

// ---------------- K5: streaming epilogue ----------------
// grid (16 ntiles, 32 cgroups, Bdim), 256 thr. Block: 8 channels x 1024 px.
// s tile cached in smem (kills L2 s-traffic).
__global__ __launch_bounds__(256)
void k5_final(const float* __restrict__ x, float* __restrict__ out){
  const int nt = blockIdx.x, cgr = blockIdx.y, b = blockIdx.z;
  const int t = threadIdx.x, warp = t>>5, lane = t&31;
  __shared__ float4 s_s[256];
  s_s[t] = ((const float4*)g_s)[(size_t)b*4096 + nt*256 + t];
  __syncthreads();

  int c = cgr*8 + warp;
  float cf = __ldg(&g_cf[b*Cdim + c]);
  size_t base = ((size_t)(b*Cdim + c))*4096 + nt*256;
  const float4* xc = (const float4*)x + base;
  float4* oc = (float4*)out + base;
  #pragma unroll
  for (int i=0;i<8;i++){
    float4 xv = xc[i*32 + lane];
    float4 sv = s_s[i*32 + lane];
    float4 o;
    o.x = fmaf(sv.x, cf, xv.x);
    o.y = fmaf(sv.y, cf, xv.y);
    o.z = fmaf(sv.z, cf, xv.z);
    o.w = fmaf(sv.w, cf, xv.w);
    oc[i*32 + lane] = o;
  }
}

// ---------------- launch ----------------
extern "C" void kernel_launch(void* const* d_in, const int* in_sizes, int n_in,
                              void* d_out, int out_size){
  const float* x  = (const float*)d_in[0];
  const float* vw = (const float*)d_in[1];
  const float* vb = (const float*)d_in[2];
  const float* kw = (const float*)d_in[3];
  const float* kb = (const float*)d_in[4];
  const float* w1 = (const float*)d_in[5];
  const float* b1 = (const float*)d_in[6];
  const float* w2 = (const float*)d_in[7];
  const float* b2 = (const float*)d_in[8];
  const float* w3 = (const float*)d_in[9];
  const float* b3 = (const float*)d_in[10];
  float* out = (float*)d_out;

  k0_init<<<1,256>>>(vw, vb, w3);
  k1_partial<<<dim3(NT,NCG,Bdim),256>>>(x, kw);
  k2a_logits<<<dim3(NT,Bdim),256>>>(kb);
  k2b_combine<<<Bdim,256>>>(w1, b1, w2, b2);
  k2c_smap<<<dim3(NT,Bdim),256>>>(b3);
  k3_xk<<<dim3(NT,NCG,Bdim),256>>>(x);
  k4_cf<<<Bdim,256>>>(vw, vb);
  k5_final<<<dim3(16,32,Bdim),256>>>(x, out);
}

// round 3
// speedup vs baseline: 1.4373x; 1.0125x over previous
#include <cuda_runtime.h>
#include <cfloat>
#include <math.h>

#define Cdim 256
#define Hdim 128
#define Wdim 128
#define HW   16384
#define Bdim 8
#define NT2  64         // tiles per batch (2 rows = 256 px each)
#define TPX2 256        // pixels per tile

// ---------------- scratch (device globals) ----------------
__device__ float g_u[Cdim];             // v_w^T w3
__device__ float g_t3bias;              // w3 . v_b
__device__ float g_t3s[Bdim*HW];        // t3 per pixel
__device__ float g_s[Bdim*HW];          // final spatial sigmoid map
__device__ float g_Mt[Bdim*NT2];
__device__ float g_Zt[Bdim*NT2];
__device__ float g_ah[Bdim*Hdim];       // h attention (computed in K1, exact)
__device__ float g_aw[Bdim*Wdim];       // w attention
__device__ float g_wpm[Bdim*NT2*Wdim];  // per-tile w max partial
__device__ float g_wps[Bdim*NT2*Wdim];  // per-tile w sum partial
__device__ float g_xkp[Bdim*NT2*Cdim];  // per-tile unnormalized xk partial
__device__ float g_cf[Bdim*Cdim];       // channel_fea

// ---------------- helpers ----------------
__device__ __forceinline__ float warpMax(float v){
  #pragma unroll
  for (int o=16;o;o>>=1) v = fmaxf(v, __shfl_xor_sync(0xffffffffu, v, o));
  return v;
}
__device__ __forceinline__ float warpSum(float v){
  #pragma unroll
  for (int o=16;o;o>>=1) v += __shfl_xor_sync(0xffffffffu, v, o);
  return v;
}
__device__ __forceinline__ float sigmoidf_(float x){ return 1.f/(1.f+expf(-x)); }

// ---------------- K0: precompute u, t3bias ----------------
__global__ __launch_bounds__(256)
void k0_init(const float* __restrict__ vw, const float* __restrict__ vb,
             const float* __restrict__ w3){
  int t = threadIdx.x;
  float u = 0.f;
  #pragma unroll 8
  for (int o=0;o<Cdim;o++) u = fmaf(w3[o], vw[o*Cdim + t], u);
  g_u[t] = u;
  if (t==0){
    float tb = 0.f;
    for (int o=0;o<Cdim;o++) tb = fmaf(w3[o], vb[o], tb);
    g_t3bias = tb;
  }
}

// ---------------- K1: fully fused main pass ----------------
// grid (NT2, Bdim), 256 thr. Block: ALL 256 channels x 256 px (2 full rows).
// q = channel subgroup (4 x 64 ch), p = float4 pixel index (64).
__global__ __launch_bounds__(256)
void k1_main(const float* __restrict__ x, const float* __restrict__ kwp,
             const float* __restrict__ kbp,
             const float* __restrict__ w1, const float* __restrict__ b1){
  const int jt = blockIdx.x, b = blockIdx.y;
  const int t = threadIdx.x, q = t>>6, p = t&63, warp = t>>5, lane = t&31;

  __shared__ float s_kw[Cdim], s_u[Cdim];
  __shared__ float4 s_lp[4][64], s_tp[4][64];
  __shared__ float4 s_pm[256], s_ps[256];
  __shared__ float4 s_e4[64];
  __shared__ float  s_red[8], s_red2[8];

  s_kw[t] = kwp[t];
  s_u[t]  = g_u[t];
  __syncthreads();

  // ---- pass A: 64 channels for this thread's pixel quad ----
  const float* xb = x + ((size_t)(b*Cdim + q*64))*HW + jt*TPX2 + 4*p;
  float4 aL = make_float4(0,0,0,0), aT = make_float4(0,0,0,0);
  float4 pm = make_float4(-FLT_MAX,-FLT_MAX,-FLT_MAX,-FLT_MAX);
  float4 ps = make_float4(0,0,0,0);
  #pragma unroll 8
  for (int c=0;c<64;c++){
    float4 xv = *(const float4*)(xb + (size_t)c*HW);
    float kw = s_kw[q*64 + c], uc = s_u[q*64 + c];
    aL.x = fmaf(kw, xv.x, aL.x); aL.y = fmaf(kw, xv.y, aL.y);
    aL.z = fmaf(kw, xv.z, aL.z); aL.w = fmaf(kw, xv.w, aL.w);
    aT.x = fmaf(uc, xv.x, aT.x); aT.y = fmaf(uc, xv.y, aT.y);
    aT.z = fmaf(uc, xv.z, aT.z); aT.w = fmaf(uc, xv.w, aT.w);
    pm.x = fmaxf(pm.x, xv.x); pm.y = fmaxf(pm.y, xv.y);
    pm.z = fmaxf(pm.z, xv.z); pm.w = fmaxf(pm.w, xv.w);
    ps.x += xv.x; ps.y += xv.y; ps.z += xv.z; ps.w += xv.w;
  }
  s_lp[q][p] = aL; s_tp[q][p] = aT;
  s_pm[t] = pm;    s_ps[t] = ps;
  __syncthreads();

  // ---- logits + t3 (threads 0..63, one per pixel quad) ----
  float4 l = make_float4(0,0,0,0);
  float lm = -FLT_MAX;
  if (t < 64){
    float4 l0 = s_lp[0][t], l1 = s_lp[1][t], l2 = s_lp[2][t], l3 = s_lp[3][t];
    float4 t0 = s_tp[0][t], t1 = s_tp[1][t], t2 = s_tp[2][t], t3 = s_tp[3][t];
    const float kb = kbp[0], tb = g_t3bias;
    l.x = l0.x+l1.x+l2.x+l3.x+kb; l.y = l0.y+l1.y+l2.y+l3.y+kb;
    l.z = l0.z+l1.z+l2.z+l3.z+kb; l.w = l0.w+l1.w+l2.w+l3.w+kb;
    float4 tv;
    tv.x = t0.x+t1.x+t2.x+t3.x+tb; tv.y = t0.y+t1.y+t2.y+t3.y+tb;
    tv.z = t0.z+t1.z+t2.z+t3.z+tb; tv.w = t0.w+t1.w+t2.w+t3.w+tb;
    *(float4*)(g_t3s + (size_t)b*HW + jt*TPX2 + 4*t) = tv;
    lm = fmaxf(fmaxf(l.x,l.y), fmaxf(l.z,l.w));
    // combine channel-subgroup pools per pixel quad
    float4 cm = s_pm[t], cs = s_ps[t];
    #pragma unroll
    for (int qq=1;qq<4;qq++){
      float4 m2 = s_pm[qq*64+t], s2 = s_ps[qq*64+t];
      cm.x = fmaxf(cm.x,m2.x); cm.y = fmaxf(cm.y,m2.y);
      cm.z = fmaxf(cm.z,m2.z); cm.w = fmaxf(cm.w,m2.w);
      cs.x += s2.x; cs.y += s2.y; cs.z += s2.z; cs.w += s2.w;
    }
    s_pm[t] = cm; s_ps[t] = cs;
  }
  lm = warpMax(lm);
  if (lane==0) s_red[warp] = lm;
  __syncthreads();
  const float M = fmaxf(s_red[0], s_red[1]);

  // ---- pools: h exact (warp 0 = row 0, warp 1 = row 1), w partial ----
  float z = 0.f;
  if (t < 64){
    float4 e;
    e.x = expf(l.x-M); e.y = expf(l.y-M); e.z = expf(l.z-M); e.w = expf(l.w-M);
    s_e4[t] = e;
    z = e.x+e.y+e.z+e.w;
    float4 cm = s_pm[t], cs = s_ps[t];
    float rm = fmaxf(fmaxf(cm.x,cm.y), fmaxf(cm.z,cm.w));
    float rs = cs.x+cs.y+cs.z+cs.w;
    rm = warpMax(rm); rs = warpSum(rs);
    if (lane==0){
      int h = jt*2 + warp;
      g_ah[b*Hdim + h] = sigmoidf_(w1[0]*rm + w1[1]*(rs*(1.f/32768.f)) + b1[0]);
    }
  }
  z = warpSum(z);
  if (lane==0) s_red2[warp] = z;
  if (t < 32){
    // w partial: combine the two rows for column quad t
    float4 m0 = s_pm[t], m1 = s_pm[32+t];
    float4 s0 = s_ps[t], s1 = s_ps[32+t];
    float4 wm, ws;
    wm.x = fmaxf(m0.x,m1.x); wm.y = fmaxf(m0.y,m1.y);
    wm.z = fmaxf(m0.z,m1.z); wm.w = fmaxf(m0.w,m1.w);
    ws.x = s0.x+s1.x; ws.y = s0.y+s1.y; ws.z = s0.z+s1.z; ws.w = s0.w+s1.w;
    *(float4*)(g_wpm + ((size_t)(b*NT2+jt))*Wdim + 4*t) = wm;
    *(float4*)(g_wps + ((size_t)(b*NT2+jt))*Wdim + 4*t) = ws;
  }
  __syncthreads();
  if (t==0){
    g_Mt[b*NT2 + jt] = M;
    g_Zt[b*NT2 + jt] = s_red2[0] + s_red2[1];
  }

  // ---- pass B: xk partial, tile re-read (L2-hot), descending for recency ----
  const float* xt = x + (size_t)b*Cdim*HW + jt*TPX2;
  float4 e0 = s_e4[lane], e1 = s_e4[32+lane];
  #pragma unroll 1
  for (int k=31;k>=0;k--){
    int c = warp*32 + k;
    const float4* xc = (const float4*)(xt + (size_t)c*HW);
    float4 x0 = xc[lane], x1 = xc[32+lane];
    float acc;
    acc = x0.x*e0.x + x0.y*e0.y;
    acc = fmaf(x0.z, e0.z, acc); acc = fmaf(x0.w, e0.w, acc);
    acc = fmaf(x1.x, e1.x, acc); acc = fmaf(x1.y, e1.y, acc);
    acc = fmaf(x1.z, e1.z, acc); acc = fmaf(x1.w, e1.w, acc);
    acc = warpSum(acc);
    if (lane==0) g_xkp[((size_t)(b*NT2+jt))*Cdim + c] = acc;
  }
}

// ---------------- K2b: w attention ----------------
// grid (Bdim), 512 thr: 4 threads per column, 16 tiles each.
__global__ __launch_bounds__(512)
void k2b_watt(const float* __restrict__ w2, const float* __restrict__ b2){
  const int b = blockIdx.x, t = threadIdx.x;
  const int col = t & 127, part = t >> 7;
  __shared__ float s_m[512], s_s[512];
  float m = -FLT_MAX, s = 0.f;
  #pragma unroll 16
  for (int j16=0;j16<16;j16++){
    int j = part*16 + j16;
    size_t idx = ((size_t)(b*NT2+j))*Wdim + col;
    m = fmaxf(m, g_wpm[idx]);
    s += g_wps[idx];
  }
  s_m[t] = m; s_s[t] = s;
  __syncthreads();
  if (t < 128){
    float mm = s_m[t], ss = s_s[t];
    #pragma unroll
    for (int pp=1;pp<4;pp++){
      mm = fmaxf(mm, s_m[pp*128+t]); ss += s_s[pp*128+t];
    }
    g_aw[b*Wdim + t] = sigmoidf_(w2[0]*mm + w2[1]*(ss*(1.f/32768.f)) + b2[0]);
  }
}

// ---------------- K2c: s map ----------------
// grid (16, Bdim), 256 thr, 1 float4/thread
__global__ __launch_bounds__(256)
void k2c_smap(const float* __restrict__ b3p){
  const int b = blockIdx.y;
  const int v = blockIdx.x*256 + threadIdx.x;   // f4 index in [0,4096)
  const float b3 = b3p[0];
  int n = 4*v;
  int h = n >> 7, w0 = n & 127;
  float ah = g_ah[b*Hdim + h];
  float4 t3 = ((const float4*)(g_t3s + (size_t)b*HW))[v];
  float4 s;
  s.x = sigmoidf_((ah + g_aw[b*Wdim + w0+0])*t3.x + b3);
  s.y = sigmoidf_((ah + g_aw[b*Wdim + w0+1])*t3.y + b3);
  s.z = sigmoidf_((ah + g_aw[b*Wdim + w0+2])*t3.z + b3);
  s.w = sigmoidf_((ah + g_aw[b*Wdim + w0+3])*t3.w + b3);
  ((float4*)(g_s + (size_t)b*HW))[v] = s;
}

// ---------------- K4: alpha + xk + channel_fea ----------------
// grid (Bdim), 256 thr
__global__ __launch_bounds__(256)
void k4_cf(const float* __restrict__ vw, const float* __restrict__ vb){
  const int b = blockIdx.x, t = threadIdx.x;
  const int warp = t>>5, lane = t&31;
  __shared__ float s_alpha[NT2], s_xk[Cdim], s_red[8];
  __shared__ float sM, sZ;

  // alpha: two warps cover the 64 tiles
  float m = (t < NT2) ? g_Mt[b*NT2 + t] : -FLT_MAX;
  float mm = warpMax(m);
  if (lane==0) s_red[warp] = mm;
  __syncthreads();
  if (t==0) sM = fmaxf(s_red[0], s_red[1]);
  __syncthreads();
  float ze = (t < NT2) ? g_Zt[b*NT2 + t]*expf(m - sM) : 0.f;
  float zz = warpSum(ze);
  if (lane==0) s_red[warp] = zz;
  __syncthreads();
  if (t==0) sZ = s_red[0] + s_red[1];
  __syncthreads();
  if (t < NT2) s_alpha[t] = expf(m - sM)/sZ;
  __syncthreads();

  // xk[c] = sum_j xkp[j][c] * alpha[j]
  float xk = 0.f;
  #pragma unroll 8
  for (int j=0;j<NT2;j++)
    xk = fmaf(g_xkp[((size_t)(b*NT2+j))*Cdim + t], s_alpha[j], xk);
  s_xk[t] = xk;
  __syncthreads();

  float cf = vb[t];
  #pragma unroll 8
  for (int c=0;c<Cdim;c++) cf = fmaf(vw[t*Cdim + c], s_xk[c], cf);
  g_cf[b*Cdim + t] = cf;
}

// ---------------- K5: streaming epilogue ----------------
// grid (16, 32, Bdim), 256 thr. Block: 8 channels x 1024 px, s tile in smem.
__global__ __launch_bounds__(256)
void k5_final(const float* __restrict__ x, float* __restrict__ out){
  const int nt = blockIdx.x, cgr = blockIdx.y, b = blockIdx.z;
  const int t = threadIdx.x, warp = t>>5, lane = t&31;
  __shared__ float4 s_s[256];
  s_s[t] = ((const float4*)g_s)[(size_t)b*4096 + nt*256 + t];
  __syncthreads();

  int c = cgr*8 + warp;
  float cf = __ldg(&g_cf[b*Cdim + c]);
  size_t base = ((size_t)(b*Cdim + c))*4096 + nt*256;
  const float4* xc = (const float4*)x + base;
  float4* oc = (float4*)out + base;
  #pragma unroll
  for (int i=0;i<8;i++){
    float4 xv = xc[i*32 + lane];
    float4 sv = s_s[i*32 + lane];
    float4 o;
    o.x = fmaf(sv.x, cf, xv.x);
    o.y = fmaf(sv.y, cf, xv.y);
    o.z = fmaf(sv.z, cf, xv.z);
    o.w = fmaf(sv.w, cf, xv.w);
    oc[i*32 + lane] = o;
  }
}

// ---------------- launch ----------------
extern "C" void kernel_launch(void* const* d_in, const int* in_sizes, int n_in,
                              void* d_out, int out_size){
  const float* x  = (const float*)d_in[0];
  const float* vw = (const float*)d_in[1];
  const float* vb = (const float*)d_in[2];
  const float* kw = (const float*)d_in[3];
  const float* kb = (const float*)d_in[4];
  const float* w1 = (const float*)d_in[5];
  const float* b1 = (const float*)d_in[6];
  const float* w2 = (const float*)d_in[7];
  const float* b2 = (const float*)d_in[8];
  const float* w3 = (const float*)d_in[9];
  const float* b3 = (const float*)d_in[10];
  float* out = (float*)d_out;

  k0_init<<<1,256>>>(vw, vb, w3);
  k1_main<<<dim3(NT2,Bdim),256>>>(x, kw, kb, w1, b1);
  k2b_watt<<<Bdim,512>>>(w2, b2);
  k2c_smap<<<dim3(16,Bdim),256>>>(b3);
  k4_cf<<<Bdim,256>>>(vw, vb);
  k5_final<<<dim3(16,32,Bdim),256>>>(x, out);
}